// round 17
// baseline (speedup 1.0000x reference)
#include <cuda_runtime.h>
#include <cuda_fp16.h>
#include <mma.h>
#include <math.h>
#include <stdint.h>

using namespace nvcuda;

#define T_STEPS 1024
#define BATCH   256
#define E_DIM   128

__device__ float  g_xproj[134217728];   // x_proj fp32 [M][512]
__device__ __half g_xh16[67108864];     // x fp16 [M=262144][256]
__device__ __half g_wh[131072];         // W_ih fp16 [512][256]

// ---------------------------------------------------------------------------
// helpers
// ---------------------------------------------------------------------------
__device__ __forceinline__ uint32_t smem_u32(const void* p) {
    uint32_t a;
    asm("{ .reg .u64 t; cvta.to.shared.u64 t, %1; cvt.u32.u64 %0, t; }" : "=r"(a) : "l"(p));
    return a;
}
__device__ __forceinline__ void cp16(uint32_t dst, const void* src) {
    asm volatile("cp.async.cg.shared.global [%0], [%1], 16;" :: "r"(dst), "l"(src));
}
__device__ __forceinline__ void cp_commit() { asm volatile("cp.async.commit_group;"); }
__device__ __forceinline__ void cp_wait0()  { asm volatile("cp.async.wait_group 0;"); }
__device__ __forceinline__ void cp_wait1()  { asm volatile("cp.async.wait_group 1;"); }
__device__ __forceinline__ void cp_wait2()  { asm volatile("cp.async.wait_group 2;"); }
__device__ __forceinline__ void mma16816h(float* c, const uint32_t* a, uint32_t b0, uint32_t b1) {
    asm volatile(
        "mma.sync.aligned.m16n8k16.row.col.f32.f16.f16.f32 "
        "{%0,%1,%2,%3}, {%4,%5,%6,%7}, {%8,%9}, {%0,%1,%2,%3};"
        : "+f"(c[0]), "+f"(c[1]), "+f"(c[2]), "+f"(c[3])
        : "r"(a[0]), "r"(a[1]), "r"(a[2]), "r"(a[3]), "r"(b0), "r"(b1));
}
__device__ __forceinline__ uint32_t pkhf(float x, float y) {
    __half2 h = __floats2half2_rn(x, y);
    return *reinterpret_cast<uint32_t*>(&h);
}
__device__ __forceinline__ float tanha(float x) {
    float r;
    asm("tanh.approx.f32 %0, %1;" : "=f"(r) : "f"(x));
    return r;
}
__device__ __forceinline__ float sigma_(float x) {
    return fmaf(0.5f, tanha(0.5f * x), 0.5f);
}

// ---------------------------------------------------------------------------
// Prep: x -> fp16, W_ih -> fp16 (validated R15)
// ---------------------------------------------------------------------------
__global__ void prep_x16(const float* __restrict__ x) {
    const int stride = gridDim.x * blockDim.x;
    for (int u = blockIdx.x * blockDim.x + threadIdx.x; u < 16777216; u += stride) {
        float4 v = reinterpret_cast<const float4*>(x)[u];
        uint2 ph;
        ph.x = ((uint32_t)__half_as_ushort(__float2half_rn(v.y)) << 16) |
               __half_as_ushort(__float2half_rn(v.x));
        ph.y = ((uint32_t)__half_as_ushort(__float2half_rn(v.w)) << 16) |
               __half_as_ushort(__float2half_rn(v.z));
        reinterpret_cast<uint2*>(g_xh16)[u] = ph;
    }
}
__global__ void prep_w(const float* __restrict__ W) {
    int u = blockIdx.x * blockDim.x + threadIdx.x;
    if (u < 32768) {
        float4 v = reinterpret_cast<const float4*>(W)[u];
        uint2 ph;
        ph.x = ((uint32_t)__half_as_ushort(__float2half_rn(v.y)) << 16) |
               __half_as_ushort(__float2half_rn(v.x));
        ph.y = ((uint32_t)__half_as_ushort(__float2half_rn(v.w)) << 16) |
               __half_as_ushort(__float2half_rn(v.z));
        reinterpret_cast<uint2*>(g_wh)[u] = ph;
    }
}

// ---------------------------------------------------------------------------
// Kernel 1: x_proj GEMM fp16 wmma (validated R15, ~280us). Unchanged.
// ---------------------------------------------------------------------------
#define HP 72
#define A_ST (128 * HP)
#define W_ST (256 * HP)
#define GEMM_SMEM ((2 * A_ST + 2 * W_ST) * 2 + 16 * 260 * 4)

__global__ __launch_bounds__(256, 1)
void xproj_gemm_h(const float* __restrict__ bih, const float* __restrict__ bhh)
{
    extern __shared__ __half hsm[];
    __half* Asm = hsm;
    __half* Wsm = hsm + 2 * A_ST;
    float* BiasT = reinterpret_cast<float*>(hsm + 2 * A_ST + 2 * W_ST);

    const int n0  = blockIdx.x * 256;
    const int m0  = blockIdx.y * 128;
    const int tid = threadIdx.x;
    const int warp = tid >> 5;
    const int wm = (warp >> 2) * 64;
    const int wn = (warp & 3) * 64;

    const uint32_t a_b = smem_u32(Asm);
    const uint32_t w_b = smem_u32(Wsm);

    for (int i = tid; i < 16 * 256; i += 256) {
        int r = i >> 8, c = i & 255;
        BiasT[r * 260 + c] = bih[n0 + c] + bhh[n0 + c];
    }
    __syncthreads();

    wmma::fragment<wmma::accumulator, 16, 16, 16, float> cf[4][4];
#pragma unroll
    for (int i = 0; i < 4; i++)
#pragma unroll
        for (int j = 0; j < 4; j++)
            wmma::load_matrix_sync(cf[i][j], &BiasT[wn + j * 16], 260, wmma::mem_row_major);
    __syncthreads();

    auto issue = [&](int kt, int s) {
#pragma unroll
        for (int it = 0; it < 4; it++) {
            int u = tid + it * 256;
            int row = u >> 3, ko = (u & 7) * 8;
            cp16(a_b + (uint32_t)(s * A_ST + row * HP + ko) * 2,
                 &g_xh16[(size_t)(m0 + row) * 256 + kt * 64 + ko]);
        }
#pragma unroll
        for (int it = 0; it < 8; it++) {
            int u = tid + it * 256;
            int row = u >> 3, ko = (u & 7) * 8;
            cp16(w_b + (uint32_t)(s * W_ST + row * HP + ko) * 2,
                 &g_wh[(size_t)(n0 + row) * 256 + kt * 64 + ko]);
        }
        cp_commit();
    };

    issue(0, 0);
    for (int kt = 0; kt < 4; kt++) {
        const int s = kt & 1;
        if (kt < 3) { issue(kt + 1, s ^ 1); cp_wait1(); }
        else        { cp_wait0(); }
        __syncthreads();
        const __half* As = Asm + s * A_ST;
        const __half* Ws = Wsm + s * W_ST;
#pragma unroll
        for (int kk = 0; kk < 64; kk += 16) {
            wmma::fragment<wmma::matrix_a, 16, 16, 16, __half, wmma::row_major> af[4];
            wmma::fragment<wmma::matrix_b, 16, 16, 16, __half, wmma::col_major> bf[4];
#pragma unroll
            for (int i = 0; i < 4; i++)
                wmma::load_matrix_sync(af[i], &As[(wm + i * 16) * HP + kk], HP);
#pragma unroll
            for (int j = 0; j < 4; j++)
                wmma::load_matrix_sync(bf[j], &Ws[(wn + j * 16) * HP + kk], HP);
#pragma unroll
            for (int i = 0; i < 4; i++)
#pragma unroll
                for (int j = 0; j < 4; j++)
                    wmma::mma_sync(cf[i][j], af[i], bf[j], cf[i][j]);
        }
        __syncthreads();
    }
#pragma unroll
    for (int i = 0; i < 4; i++)
#pragma unroll
        for (int j = 0; j < 4; j++)
            wmma::store_matrix_sync(
                &g_xproj[(size_t)(m0 + wm + i * 16) * 512 + n0 + wn + j * 16],
                cf[i][j], 512, wmma::mem_row_major);
}

// ---------------------------------------------------------------------------
// Recurrence: 32-warp m-split. 64 CTAs x 4 batches, 1024 threads.
// Warp (q = w&3, mh = w>>2) owns gate rows q*128 + mh*16 (+0..15):
// 1 m16-tile x 8 kt = 8 HMMA/warp in two 4-deep chains. Gates via gsm,
// epilogue/state on tid<512 (1 item each). 2 bars/step.
// ---------------------------------------------------------------------------
__device__ __forceinline__ void bt_write(char* bt, int e, int col, unsigned short v) {
    int kt = e >> 4, kk = e & 15;
    int half = kk >> 3, tq = (kk & 7) >> 1, lo2 = kk & 1;
    *reinterpret_cast<unsigned short*>(bt + kt * 256 + (col * 4 + tq) * 8 + half * 4 + lo2 * 2) = v;
}

__global__ __launch_bounds__(1024, 1)
void lstm_rec_m32(const float* __restrict__ Whh,
                  const float* __restrict__ h0,
                  const float* __restrict__ c0,
                  float* __restrict__ out)
{
    __shared__ __align__(16) char  Btile[2][2048];
    __shared__ __align__(16) float gsm[2048];        // [512 rows][4 batches]
    __shared__ __align__(16) float xring[4][2048];   // 32 KB

    const int tid = threadIdx.x;
    const int w   = tid >> 5;
    const int l   = tid & 31;
    const int q   = w & 3;           // gate type
    const int mh  = w >> 2;          // row-group (0..7)
    const int bg0 = blockIdx.x * 4;
    const int g0  = q * 128 + mh * 16;

    // ---- W_hh fp16 A-fragments: 1 m16-tile x 8 kt ----
    uint32_t wf[8][4];
    {
        const int t2 = 2 * (l & 3);
        const int r0 = g0 + (l >> 2);
#pragma unroll
        for (int kt = 0; kt < 8; kt++) {
            int k0 = kt * 16 + t2;
            const float* p00 = &Whh[(size_t)r0 * 128 + k0];
            const float* p10 = &Whh[(size_t)(r0 + 8) * 128 + k0];
            wf[kt][0] = pkhf(p00[0], p00[1]);
            wf[kt][1] = pkhf(p10[0], p10[1]);
            wf[kt][2] = pkhf(p00[8], p00[9]);
            wf[kt][3] = pkhf(p10[8], p10[9]);
        }
    }

    // ---- state: tid<512 owns 1 item (e, b) ----
    const int e = (tid & 511) >> 2;
    const int b = tid & 3;
    float creg = 0.f, hprev = 0.f;
    if (tid < 512) {
        creg = c0[(size_t)(bg0 + b) * 128 + e];
        float h = h0[(size_t)(bg0 + b) * 128 + e];
        __half hh = __float2half_rn(h);
        __half hl = __float2half_rn(h - __half2float(hh));
        bt_write(Btile[0], e, b,     __half_as_ushort(hh));
        bt_write(Btile[0], e, b + 4, __half_as_ushort(hl));
    }

    // ---- xring: tid<512 copies 4 floats/stage ----
    const uint32_t xr_b = smem_u32(xring);
    auto xissue = [&](int t) {
        if (t < T_STEPS && tid < 512)
            cp16(xr_b + (uint32_t)((t & 3) * 8192 + tid * 16),
                 &g_xproj[((size_t)t * BATCH + bg0 + (tid >> 7)) * 512 + (tid & 127) * 4]);
        cp_commit();
    };
    xissue(0); xissue(1); xissue(2);
    cp_wait2();
    __syncthreads();

    const bool writer = (l & 3) < 2;

    for (int t = 0; t < T_STEPS; t++) {
        const char* bt_rd = Btile[t & 1];
        char* bt_wr = Btile[(t + 1) & 1];

        // deferred softplus + STG for t-1 (overlaps MMA)
        if (t > 0 && tid < 512)
            out[((size_t)(t - 1) * BATCH + bg0 + b) * E_DIM + e] =
                __logf(1.f + __expf(hprev));

        // ---- MMA sweep: 8 HMMA, two 4-deep chains ----
        float accA[4] = {0.f, 0.f, 0.f, 0.f};
        float accB[4] = {0.f, 0.f, 0.f, 0.f};
#pragma unroll
        for (int kt = 0; kt < 8; kt++) {
            uint2 bv = *reinterpret_cast<const uint2*>(bt_rd + kt * 256 + l * 8);
            mma16816h((kt < 4) ? accA : accB, wf[kt], bv.x, bv.y);
        }

        // ---- hi/lo butterfly + gate STS ----
#pragma unroll
        for (int c = 0; c < 4; c++) {
            float v = accA[c] + accB[c];
            v += __shfl_xor_sync(0xffffffffu, v, 2);
            if (writer) {
                int row = g0 + (l >> 2) + 8 * (c >> 1);
                int bb  = 2 * (l & 3) + (c & 1);
                gsm[row * 4 + bb] = v;
            }
        }
        __syncthreads();   // bar1: gates visible; all bt_rd reads done

        // ---- epilogue: tid<512, 1 item each ----
        if (tid < 512) {
            const float* xrow = xring[t & 3] + b * 512 + e;
            float gi = gsm[0 * 512 + tid] + xrow[0];
            float gf = gsm[1 * 512 + tid] + xrow[128];
            float gg = gsm[2 * 512 + tid] + xrow[256];
            float go = gsm[3 * 512 + tid] + xrow[384];
            float i_ = sigma_(gi), f_ = sigma_(gf), o_ = sigma_(go);
            float g_ = tanha(gg);
            creg = f_ * creg + i_ * g_;
            float h = o_ * tanha(creg);
            __half hh = __float2half_rn(h);
            __half hl = __float2half_rn(h - __half2float(hh));
            bt_write(bt_wr, e, b,     __half_as_ushort(hh));
            bt_write(bt_wr, e, b + 4, __half_as_ushort(hl));
            hprev = h;
        }

        xissue(t + 3);
        cp_wait2();
        __syncthreads();   // bar2: bt_wr + ring visible; gsm reusable
    }

    if (tid < 512)
        out[((size_t)(T_STEPS - 1) * BATCH + bg0 + b) * E_DIM + e] =
            __logf(1.f + __expf(hprev));
}

// ---------------------------------------------------------------------------
extern "C" void kernel_launch(void* const* d_in, const int* in_sizes, int n_in,
                              void* d_out, int out_size)
{
    const float* x   = (const float*)d_in[0];
    const float* h0  = (const float*)d_in[1];
    const float* c0  = (const float*)d_in[2];
    const float* Wih = (const float*)d_in[3];
    const float* Whh = (const float*)d_in[4];
    const float* bih = (const float*)d_in[5];
    const float* bhh = (const float*)d_in[6];
    float* out = (float*)d_out;

    cudaFuncSetAttribute((const void*)xproj_gemm_h,
                         cudaFuncAttributeMaxDynamicSharedMemorySize, GEMM_SMEM);

    prep_x16<<<2048, 256>>>(x);
    prep_w<<<128, 256>>>(Wih);
    xproj_gemm_h<<<dim3(2, 2048), 256, GEMM_SMEM>>>(bih, bhh);
    lstm_rec_m32<<<64, 1024>>>(Whh, h0, c0, out);
}